// round 1
// baseline (speedup 1.0000x reference)
#include <cuda_runtime.h>
#include <cuda_bf16.h>

// Problem constants
#define B_   4
#define CIN  64
#define C_   256
#define N_   1729          // 1 cls + 12*12*12 tokens
#define P_   1728
#define NH   8
#define HD   32
#define DEPTH 2
#define M_TOK (B_ * N_)    // 6916

// Scratch (device globals; no cudaMalloc allowed)
__device__ float g_t  [M_TOK * C_];
__device__ float g_y  [M_TOK * C_];
__device__ float g_qkv[M_TOK * 3 * C_];
__device__ float g_o  [M_TOK * C_];
__device__ float g_h  [M_TOK * C_];

// ---------------------------------------------------------------------------
// Patch embed + cls token:  t[b,0,:] = cls ; t[b,1+p,d] = sum_c x[b,c,p]*W_pe[c,d] + b_pe[d]
// ---------------------------------------------------------------------------
__global__ void embed_kernel(const float* __restrict__ x,
                             const float* __restrict__ W_pe,
                             const float* __restrict__ b_pe,
                             const float* __restrict__ cls) {
    int n = blockIdx.x;          // 0..1728
    int b = blockIdx.y;          // 0..3
    int d = threadIdx.x;         // 0..255
    if (n == 0) {
        g_t[(b * N_) * C_ + d] = cls[d];
        return;
    }
    int p = n - 1;
    __shared__ float sx[CIN];
    if (d < CIN) sx[d] = x[(b * CIN + d) * P_ + p];
    __syncthreads();
    float acc = b_pe[d];
#pragma unroll
    for (int c = 0; c < CIN; c++) acc += sx[c] * W_pe[c * C_ + d];
    g_t[(b * N_ + n) * C_ + d] = acc;
}

// ---------------------------------------------------------------------------
// LayerNorm over last dim (256). One block (256 threads) per token row.
// ---------------------------------------------------------------------------
__device__ __forceinline__ float ln_value(const float* __restrict__ in, int row, int tid,
                                          const float* __restrict__ g,
                                          const float* __restrict__ bb) {
    float v = in[row * C_ + tid];
    float s = v, sq = v * v;
#pragma unroll
    for (int o = 16; o > 0; o >>= 1) {
        s  += __shfl_down_sync(0xffffffffu, s,  o);
        sq += __shfl_down_sync(0xffffffffu, sq, o);
    }
    __shared__ float rs[8], rq[8];
    int wid = tid >> 5, lid = tid & 31;
    if (lid == 0) { rs[wid] = s; rq[wid] = sq; }
    __syncthreads();
    float sum = 0.f, sumq = 0.f;
#pragma unroll
    for (int i = 0; i < 8; i++) { sum += rs[i]; sumq += rq[i]; }
    float mean = sum * (1.f / C_);
    float var  = sumq * (1.f / C_) - mean * mean;
    float inv  = rsqrtf(var + 1e-5f);
    return (v - mean) * inv * g[tid] + bb[tid];
}

__global__ void ln_kernel(const float* __restrict__ in, float* __restrict__ out,
                          const float* __restrict__ g, const float* __restrict__ bb) {
    int row = blockIdx.x;
    int tid = threadIdx.x;
    out[row * C_ + tid] = ln_value(in, row, tid, g, bb);
}

// Final LN + scatter to output layout: x_cls then feat (B,C,H,W,L)
__global__ void final_ln_kernel(const float* __restrict__ in,
                                const float* __restrict__ g, const float* __restrict__ bb,
                                float* __restrict__ out) {
    int row = blockIdx.x;            // 0..6915
    int tid = threadIdx.x;
    float val = ln_value(in, row, tid, g, bb);
    int b = row / N_, n = row % N_;
    if (n == 0) out[b * C_ + tid] = val;
    else        out[B_ * C_ + (b * C_ + tid) * P_ + (n - 1)] = val;
}

// ---------------------------------------------------------------------------
// Tiled fp32 GEMM:  out[M,N] = act(A[M,K] @ W[K,N] + bias) (+= if RES)
// BM=BN=64, BK=16, 256 threads, 4x4 micro-tile per thread.
// ---------------------------------------------------------------------------
template<bool GELU, bool RES>
__global__ void gemm_kernel(const float* __restrict__ A, const float* __restrict__ W,
                            const float* __restrict__ bias, float* __restrict__ out,
                            int M, int K, int N) {
    __shared__ float sA[16][68];   // [k][m], padded
    __shared__ float sB[16][64];   // [k][n]
    int tx = threadIdx.x & 15;
    int ty = threadIdx.x >> 4;
    int n0 = blockIdx.x * 64;
    int m0 = blockIdx.y * 64;
    float acc[4][4] = {};

    for (int k0 = 0; k0 < K; k0 += 16) {
#pragma unroll
        for (int i = 0; i < 4; i++) {
            int idx = threadIdx.x + i * 256;
            int kl = idx & 15, ml = idx >> 4;
            int m = m0 + ml;
            sA[kl][ml] = (m < M) ? A[m * K + k0 + kl] : 0.f;
        }
#pragma unroll
        for (int i = 0; i < 4; i++) {
            int idx = threadIdx.x + i * 256;
            int nl = idx & 63, kl = idx >> 6;
            int n = n0 + nl;
            sB[kl][nl] = (n < N) ? W[(k0 + kl) * N + n] : 0.f;
        }
        __syncthreads();
#pragma unroll
        for (int kk = 0; kk < 16; kk++) {
            float a[4], b4[4];
#pragma unroll
            for (int i = 0; i < 4; i++) a[i]  = sA[kk][ty * 4 + i];
#pragma unroll
            for (int j = 0; j < 4; j++) b4[j] = sB[kk][tx * 4 + j];
#pragma unroll
            for (int i = 0; i < 4; i++)
#pragma unroll
                for (int j = 0; j < 4; j++)
                    acc[i][j] += a[i] * b4[j];
        }
        __syncthreads();
    }

#pragma unroll
    for (int i = 0; i < 4; i++) {
        int m = m0 + ty * 4 + i;
        if (m >= M) continue;
#pragma unroll
        for (int j = 0; j < 4; j++) {
            int n = n0 + tx * 4 + j;
            if (n >= N) continue;
            float v = acc[i][j] + (bias ? bias[n] : 0.f);
            if (GELU) v = v * normcdff(v);   // exact gelu
            if (RES) out[m * N + n] += v;
            else     out[m * N + n]  = v;
        }
    }
}

// ---------------------------------------------------------------------------
// Fused flash attention (fp32, online softmax).
// Block = 128 threads, each thread owns one full query row (hd=32).
// Key/value tiles of 64 staged through smem (broadcast reads).
// grid = (ceil(N/128), B*NH)
// ---------------------------------------------------------------------------
__global__ __launch_bounds__(128) void attn_kernel(const float* __restrict__ qkv,
                                                   float* __restrict__ o_out) {
    int qt  = blockIdx.x;
    int bh  = blockIdx.y;
    int b   = bh >> 3;
    int h   = bh & 7;
    int tid = threadIdx.x;
    int qi  = qt * 128 + tid;

    __shared__ float sK[64 * 32];
    __shared__ float sV[64 * 32];

    const float scale = 0.17677669529663687f;   // 1/sqrt(32)

    float q[HD];
    if (qi < N_) {
        const float4* qp = (const float4*)(qkv + (b * N_ + qi) * (3 * C_) + h * HD);
#pragma unroll
        for (int i = 0; i < 8; i++) {
            float4 t = qp[i];
            q[4*i] = t.x; q[4*i+1] = t.y; q[4*i+2] = t.z; q[4*i+3] = t.w;
        }
    } else {
#pragma unroll
        for (int i = 0; i < HD; i++) q[i] = 0.f;
    }

    float o_acc[HD];
#pragma unroll
    for (int i = 0; i < HD; i++) o_acc[i] = 0.f;
    float m_run = -1e30f, l_run = 0.f;

    for (int kb = 0; kb < N_; kb += 64) {
#pragma unroll
        for (int i = 0; i < 16; i++) {
            int idx = tid + i * 128;
            int r = idx >> 5, d = idx & 31;
            int m = kb + r;
            bool ok = m < N_;
            int base = (b * N_ + (ok ? m : 0)) * (3 * C_) + h * HD + d;
            sK[idx] = ok ? qkv[base + C_]     : 0.f;
            sV[idx] = ok ? qkv[base + 2*C_]   : 0.f;
        }
        __syncthreads();

        float s[64];
        float tmax = -1e30f;
#pragma unroll 4
        for (int r = 0; r < 64; r++) {
            const float4* kp = (const float4*)(sK + r * 32);
            float dot = 0.f;
#pragma unroll
            for (int d4 = 0; d4 < 8; d4++) {
                float4 kv = kp[d4];
                dot += q[4*d4] * kv.x + q[4*d4+1] * kv.y
                     + q[4*d4+2] * kv.z + q[4*d4+3] * kv.w;
            }
            float sv = (kb + r < N_) ? dot * scale : -1e30f;
            s[r] = sv;
            tmax = fmaxf(tmax, sv);
        }

        float new_m = fmaxf(m_run, tmax);
        float corr  = __expf(m_run - new_m);
        l_run *= corr;
#pragma unroll
        for (int d = 0; d < HD; d++) o_acc[d] *= corr;

#pragma unroll 2
        for (int r = 0; r < 64; r++) {
            float p = __expf(s[r] - new_m);
            l_run += p;
            const float4* vp = (const float4*)(sV + r * 32);
#pragma unroll
            for (int d4 = 0; d4 < 8; d4++) {
                float4 vv = vp[d4];
                o_acc[4*d4]   += p * vv.x;
                o_acc[4*d4+1] += p * vv.y;
                o_acc[4*d4+2] += p * vv.z;
                o_acc[4*d4+3] += p * vv.w;
            }
        }
        m_run = new_m;
        __syncthreads();
    }

    if (qi < N_) {
        float inv = 1.f / l_run;
        float* op = o_out + (b * N_ + qi) * C_ + h * HD;
#pragma unroll
        for (int d = 0; d < HD; d++) op[d] = o_acc[d] * inv;
    }
}

// ---------------------------------------------------------------------------
// Host launch
// ---------------------------------------------------------------------------
extern "C" void kernel_launch(void* const* d_in, const int* in_sizes, int n_in,
                              void* d_out, int out_size) {
    const float* x       = (const float*)d_in[0];
    const float* W_pe    = (const float*)d_in[1];
    const float* b_pe    = (const float*)d_in[2];
    const float* cls     = (const float*)d_in[3];
    const float* ln1_g   = (const float*)d_in[4];
    const float* ln1_b   = (const float*)d_in[5];
    const float* Wqkv    = (const float*)d_in[6];
    const float* Wproj   = (const float*)d_in[7];
    const float* bproj   = (const float*)d_in[8];
    const float* ln2_g   = (const float*)d_in[9];
    const float* ln2_b   = (const float*)d_in[10];
    const float* W1      = (const float*)d_in[11];
    const float* b1      = (const float*)d_in[12];
    const float* W2      = (const float*)d_in[13];
    const float* b2      = (const float*)d_in[14];
    const float* normf_g = (const float*)d_in[15];
    const float* normf_b = (const float*)d_in[16];
    float* out = (float*)d_out;

    float *t, *y, *qkv, *o, *h;
    cudaGetSymbolAddress((void**)&t,   g_t);
    cudaGetSymbolAddress((void**)&y,   g_y);
    cudaGetSymbolAddress((void**)&qkv, g_qkv);
    cudaGetSymbolAddress((void**)&o,   g_o);
    cudaGetSymbolAddress((void**)&h,   g_h);

    const int M = M_TOK;
    dim3 gridQKV(12, (M + 63) / 64);   // N=768
    dim3 gridC(4, (M + 63) / 64);      // N=256
    dim3 gridAttn((N_ + 127) / 128, B_ * NH);

    embed_kernel<<<dim3(N_, B_), C_>>>(x, W_pe, b_pe, cls);

    for (int i = 0; i < DEPTH; i++) {
        const float* wqkv  = Wqkv  + i * C_ * 3 * C_;
        const float* wproj = Wproj + i * C_ * C_;
        const float* w1    = W1    + i * C_ * C_;
        const float* w2    = W2    + i * C_ * C_;

        ln_kernel<<<M, C_>>>(t, y, ln1_g + i * C_, ln1_b + i * C_);
        gemm_kernel<false, false><<<gridQKV, 256>>>(y, wqkv, nullptr, qkv, M, C_, 3 * C_);
        attn_kernel<<<gridAttn, 128>>>(qkv, o);
        gemm_kernel<false, true><<<gridC, 256>>>(o, wproj, bproj + i * C_, t, M, C_, C_);
        ln_kernel<<<M, C_>>>(t, y, ln2_g + i * C_, ln2_b + i * C_);
        gemm_kernel<true, false><<<gridC, 256>>>(y, w1, b1 + i * C_, h, M, C_, C_);
        gemm_kernel<false, true><<<gridC, 256>>>(h, w2, b2 + i * C_, t, M, C_, C_);
    }

    final_ln_kernel<<<M, C_>>>(t, normf_g, normf_b, out);
}